// round 6
// baseline (speedup 1.0000x reference)
#include <cuda_runtime.h>

// ---------------------------------------------------------------------------
// T5 self-attention, fused:  out = Attn(X Wq^T, X Wk^T, X Wv^T) Wo^T
// Stage 1: QKV projections (one launch, z-indexed; GEMM-NT, packed f32x2 FMA)
// Stage 2: flash-attention per (b, h, q-tile) with T5 relative-position bias
// Stage 3: output projection (same GEMM)
// ---------------------------------------------------------------------------

#define B_     4
#define S_     2048
#define DM_    1024
#define H_     16
#define DK_    64
#define INNER_ 1024
#define TOK_   (B_ * S_)

typedef unsigned long long u64;

// ---- packed f32x2 helpers (Blackwell FFMA2 path) --------------------------
__device__ __forceinline__ u64 pk2(float lo, float hi) {
    u64 r; asm("mov.b64 %0, {%1, %2};" : "=l"(r) : "f"(lo), "f"(hi)); return r;
}
__device__ __forceinline__ float2 upk(u64 v) {
    float2 r; asm("mov.b64 {%0, %1}, %2;" : "=f"(r.x), "=f"(r.y) : "l"(v)); return r;
}
__device__ __forceinline__ u64 f2fma(u64 a, u64 b, u64 c) {
    u64 d; asm("fma.rn.f32x2 %0, %1, %2, %3;" : "=l"(d) : "l"(a), "l"(b), "l"(c)); return d;
}
__device__ __forceinline__ u64 f2mul(u64 a, u64 b) {
    u64 d; asm("mul.rn.f32x2 %0, %1, %2;" : "=l"(d) : "l"(a), "l"(b)); return d;
}

// ---- scratch (device globals: no allocations allowed) ---------------------
__device__ float g_q[TOK_ * INNER_];
__device__ float g_k[TOK_ * INNER_];
__device__ float g_v[TOK_ * INNER_];
__device__ float g_ctx[TOK_ * INNER_];

// ---------------------------------------------------------------------------
// GEMM core:  C[M,N] = A[M,K] * W[N,K]^T   (both operands K-contiguous)
// Block tile 128x64, BK=16, 256 threads, 8x4 per-thread micro-tile,
// f32x2 accumulators (pairs packed along M), register-prefetch pipeline.
// Requires M%128==0, N%64==0, K%16==0.
// ---------------------------------------------------------------------------
__device__ __forceinline__ void gemm_nt_body(
    const float* __restrict__ A, const float* __restrict__ W,
    float* __restrict__ C, int M, int N, int K)
{
    __shared__ float As[16 * 128];   // [k][m]  (transposed)
    __shared__ float Ws[16 * 66];    // [k][n]  stride 66 (padded)

    const int tid = threadIdx.x;
    const int tn  = tid & 15;        // 0..15 -> 4 cols each
    const int tm  = tid >> 4;        // 0..15 -> 8 rows each
    const int bm  = blockIdx.y * 128;
    const int bn  = blockIdx.x * 64;
    const int KT  = K >> 4;

    // loader coordinates
    const int am0 = tid >> 2;              // 0..63 (A rows, +64 for 2nd half)
    const int ak4 = (tid & 3) << 2;        // k offset {0,4,8,12}
    const int wn  = tid >> 2;              // 0..63 (W rows)

    const float* Ap0 = A + (size_t)(bm + am0) * K + ak4;
    const float* Ap1 = Ap0 + (size_t)64 * K;
    const float* Wp  = W + (size_t)(bn + wn) * K + ak4;

    u64 acc[4][4];
    #pragma unroll
    for (int p = 0; p < 4; p++)
        #pragma unroll
        for (int j = 0; j < 4; j++) acc[p][j] = 0ull;

    float4 pa0 = *(const float4*)(Ap0);
    float4 pa1 = *(const float4*)(Ap1);
    float4 pw  = *(const float4*)(Wp);

    for (int kt = 0; kt < KT; ++kt) {
        // stage regs -> smem (transpose A and W into [k][*])
        {
            float a0[4], a1[4], wv[4];
            *(float4*)a0 = pa0; *(float4*)a1 = pa1; *(float4*)wv = pw;
            #pragma unroll
            for (int c = 0; c < 4; c++) {
                As[(ak4 + c) * 128 + am0]      = a0[c];
                As[(ak4 + c) * 128 + am0 + 64] = a1[c];
                Ws[(ak4 + c) * 66 + wn]        = wv[c];
            }
        }
        __syncthreads();

        // prefetch next tile while computing this one
        if (kt + 1 < KT) {
            Ap0 += 16; Ap1 += 16; Wp += 16;
            pa0 = *(const float4*)(Ap0);
            pa1 = *(const float4*)(Ap1);
            pw  = *(const float4*)(Wp);
        }

        #pragma unroll
        for (int k = 0; k < 16; k++) {
            const float* asr = &As[k * 128 + 8 * tm];
            u64 a0 = *(const u64*)(asr + 0);
            u64 a1 = *(const u64*)(asr + 2);
            u64 a2 = *(const u64*)(asr + 4);
            u64 a3 = *(const u64*)(asr + 6);
            float2 w0 = *(const float2*)&Ws[k * 66 + 4 * tn];
            float2 w1 = *(const float2*)&Ws[k * 66 + 4 * tn + 2];
            u64 b0 = pk2(w0.x, w0.x), b1 = pk2(w0.y, w0.y);
            u64 b2 = pk2(w1.x, w1.x), b3 = pk2(w1.y, w1.y);
            acc[0][0] = f2fma(a0, b0, acc[0][0]); acc[0][1] = f2fma(a0, b1, acc[0][1]);
            acc[0][2] = f2fma(a0, b2, acc[0][2]); acc[0][3] = f2fma(a0, b3, acc[0][3]);
            acc[1][0] = f2fma(a1, b0, acc[1][0]); acc[1][1] = f2fma(a1, b1, acc[1][1]);
            acc[1][2] = f2fma(a1, b2, acc[1][2]); acc[1][3] = f2fma(a1, b3, acc[1][3]);
            acc[2][0] = f2fma(a2, b0, acc[2][0]); acc[2][1] = f2fma(a2, b1, acc[2][1]);
            acc[2][2] = f2fma(a2, b2, acc[2][2]); acc[2][3] = f2fma(a2, b3, acc[2][3]);
            acc[3][0] = f2fma(a3, b0, acc[3][0]); acc[3][1] = f2fma(a3, b1, acc[3][1]);
            acc[3][2] = f2fma(a3, b2, acc[3][2]); acc[3][3] = f2fma(a3, b3, acc[3][3]);
        }
        __syncthreads();
    }

    // epilogue
    #pragma unroll
    for (int p = 0; p < 4; p++) {
        float2 c0 = upk(acc[p][0]), c1 = upk(acc[p][1]);
        float2 c2 = upk(acc[p][2]), c3 = upk(acc[p][3]);
        int r0 = bm + 8 * tm + 2 * p;
        float4 lo = make_float4(c0.x, c1.x, c2.x, c3.x);
        float4 hi = make_float4(c0.y, c1.y, c2.y, c3.y);
        *(float4*)&C[(size_t)r0 * N + bn + 4 * tn]       = lo;
        *(float4*)&C[(size_t)(r0 + 1) * N + bn + 4 * tn] = hi;
    }
}

// Plain GEMM (out projection)
__global__ void __launch_bounds__(256) gemm_nt(
    const float* __restrict__ A, const float* __restrict__ W,
    float* __restrict__ C, int M, int N, int K)
{
    gemm_nt_body(A, W, C, M, N, K);
}

// Fused QKV: blockIdx.z selects weight + destination (one launch, 3x blocks)
__global__ void __launch_bounds__(256) gemm_qkv(
    const float* __restrict__ A,
    const float* __restrict__ Wq, const float* __restrict__ Wk,
    const float* __restrict__ Wv,
    float* __restrict__ Q, float* __restrict__ Kd, float* __restrict__ V)
{
    const float* W; float* C;
    if (blockIdx.z == 0)      { W = Wq; C = Q;  }
    else if (blockIdx.z == 1) { W = Wk; C = Kd; }
    else                      { W = Wv; C = V;  }
    gemm_nt_body(A, W, C, TOK_, INNER_, DM_);
}

// ---------------------------------------------------------------------------
// T5 relative-position bucket (bidirectional, NUM_BUCKETS=32, MAX_DIST=128).
// log replaced by exact integer thresholds (verified vs fp32 reference,
// including the exact-power knife-edges |d| = 16, 64).
// ---------------------------------------------------------------------------
__device__ __forceinline__ int t5_bucket(int d) {  // d = pos_key - pos_query
    int sgn = (d > 0) ? 16 : 0;
    int a = d < 0 ? -d : d;
    int r;
    if (a < 8) r = a;
    else r = 8 + (a >= 12) + (a >= 16) + (a >= 23) + (a >= 32)
               + (a >= 46) + (a >= 64) + (a >= 91);
    return sgn + r;
}

// ---------------------------------------------------------------------------
// Flash attention, one block per (q-tile of 64, head, batch).
// 256 threads as 16x16 grid, 4x4 score micro-tile per thread.
// Smem: Qs [d][m] s64 | union{ Ks [d][n] s66 , Ps [m][n] s65 } | Vs [k][d] s64
// ---------------------------------------------------------------------------
#define ATT_SMEM_FLOATS (64*64 + 64*66 + 64*64 + 64 + 64 + 32)
#define ATT_SMEM_BYTES  (ATT_SMEM_FLOATS * 4)

__global__ void __launch_bounds__(256) attn_kernel(
    const float* __restrict__ Qg, const float* __restrict__ Kg,
    const float* __restrict__ Vg,
    const int* __restrict__ positions, const float* __restrict__ mask,
    const float* __restrict__ rel_bias, float* __restrict__ ctx)
{
    extern __shared__ float smf[];
    float* Qs    = smf;                    // 64*64, [d][m]
    float* KPs   = Qs + 64 * 64;           // 64*66: Ks [d][n] s66 / Ps [m][n] s65
    float* Vs    = KPs + 64 * 66;          // 64*64, [k][d]
    int*   posk  = (int*)(Vs + 64 * 64);   // 64
    float* maskb = (float*)(posk + 64);    // 64
    float* rb    = maskb + 64;             // 32

    const int tid = threadIdx.x;
    const int tn  = tid & 15;
    const int tm  = tid >> 4;
    const int qt  = blockIdx.x, h = blockIdx.y, b = blockIdx.z;
    const int q0  = qt * 64;

    if (tid < 32) rb[tid] = rel_bias[tid * H_ + h];

    // load Q tile (transposed to [d][m])
    {
        const float* Qb = Qg + (size_t)(b * S_ + q0) * INNER_ + h * DK_;
        for (int idx = tid; idx < 64 * 16; idx += 256) {
            int row = idx >> 4, d4 = (idx & 15) << 2;
            float4 v = *(const float4*)(Qb + (size_t)row * INNER_ + d4);
            float a[4]; *(float4*)a = v;
            #pragma unroll
            for (int c = 0; c < 4; c++) Qs[(d4 + c) * 64 + row] = a[c];
        }
    }

    int posq[4];
    #pragma unroll
    for (int i = 0; i < 4; i++) posq[i] = positions[b * S_ + q0 + 4 * tm + i];

    u64 o[4][2];
    float mrow[4], lrow[4];
    const float NEG_INF = __int_as_float(0xff800000u);
    #pragma unroll
    for (int i = 0; i < 4; i++) {
        o[i][0] = 0ull; o[i][1] = 0ull; mrow[i] = NEG_INF; lrow[i] = 0.f;
    }

    __syncthreads();

    for (int kt = 0; kt < S_ / 64; ++kt) {
        const int k0 = kt * 64;
        // ---- load K (transposed, s66) and V (natural, s64) tiles ----
        {
            const float* Kb = Kg + (size_t)(b * S_ + k0) * INNER_ + h * DK_;
            const float* Vb = Vg + (size_t)(b * S_ + k0) * INNER_ + h * DK_;
            for (int idx = tid; idx < 64 * 16; idx += 256) {
                int row = idx >> 4, d4 = (idx & 15) << 2;
                float4 kv = *(const float4*)(Kb + (size_t)row * INNER_ + d4);
                float a[4]; *(float4*)a = kv;
                #pragma unroll
                for (int c = 0; c < 4; c++) KPs[(d4 + c) * 66 + row] = a[c];
                float4 vv = *(const float4*)(Vb + (size_t)row * INNER_ + d4);
                *(float4*)&Vs[row * 64 + d4] = vv;
            }
            if (tid < 64) {
                posk[tid]  = positions[b * S_ + k0 + tid];
                maskb[tid] = -1000.0f * (1.0f - mask[b * S_ + k0 + tid]);
            }
        }
        __syncthreads();

        // ---- score GEMM: S = Q K^T (pairs packed along M) ----
        u64 sa[2][4];
        #pragma unroll
        for (int p = 0; p < 2; p++)
            #pragma unroll
            for (int j = 0; j < 4; j++) sa[p][j] = 0ull;

        #pragma unroll 4
        for (int k = 0; k < 64; k++) {
            u64 a0 = *(const u64*)&Qs[k * 64 + 4 * tm];
            u64 a1 = *(const u64*)&Qs[k * 64 + 4 * tm + 2];
            float2 w0 = *(const float2*)&KPs[k * 66 + 4 * tn];
            float2 w1 = *(const float2*)&KPs[k * 66 + 4 * tn + 2];
            u64 b0 = pk2(w0.x, w0.x), b1 = pk2(w0.y, w0.y);
            u64 b2 = pk2(w1.x, w1.x), b3 = pk2(w1.y, w1.y);
            sa[0][0] = f2fma(a0, b0, sa[0][0]); sa[1][0] = f2fma(a1, b0, sa[1][0]);
            sa[0][1] = f2fma(a0, b1, sa[0][1]); sa[1][1] = f2fma(a1, b1, sa[1][1]);
            sa[0][2] = f2fma(a0, b2, sa[0][2]); sa[1][2] = f2fma(a1, b2, sa[1][2]);
            sa[0][3] = f2fma(a0, b3, sa[0][3]); sa[1][3] = f2fma(a1, b3, sa[1][3]);
        }

        float s[4][4];
        #pragma unroll
        for (int j = 0; j < 4; j++) {
            float2 t0 = upk(sa[0][j]); s[0][j] = t0.x; s[1][j] = t0.y;
            float2 t1 = upk(sa[1][j]); s[2][j] = t1.x; s[3][j] = t1.y;
        }

        // ---- bias: relative-position bucket + mask ----
        #pragma unroll
        for (int j = 0; j < 4; j++) {
            int   nj = 4 * tn + j;
            int   pk = posk[nj];
            float mb = maskb[nj];
            #pragma unroll
            for (int i = 0; i < 4; i++) {
                int bkt = t5_bucket(pk - posq[i]);
                s[i][j] += rb[bkt] + mb;
            }
        }

        // ---- online softmax update (row groups = 16-lane segments) ----
        #pragma unroll
        for (int i = 0; i < 4; i++) {
            float mx = fmaxf(fmaxf(s[i][0], s[i][1]), fmaxf(s[i][2], s[i][3]));
            #pragma unroll
            for (int off = 8; off >= 1; off >>= 1)
                mx = fmaxf(mx, __shfl_xor_sync(0xffffffffu, mx, off, 16));
            float mnew  = fmaxf(mrow[i], mx);
            float alpha = __expf(mrow[i] - mnew);
            mrow[i] = mnew;
            float ps = 0.f;
            #pragma unroll
            for (int j = 0; j < 4; j++) {
                float p = __expf(s[i][j] - mnew);
                s[i][j] = p; ps += p;
            }
            #pragma unroll
            for (int off = 8; off >= 1; off >>= 1)
                ps += __shfl_xor_sync(0xffffffffu, ps, off, 16);
            lrow[i] = lrow[i] * alpha + ps;
            u64 al = pk2(alpha, alpha);
            o[i][0] = f2mul(o[i][0], al);
            o[i][1] = f2mul(o[i][1], al);
        }

        __syncthreads();   // everyone done reading Ks before P overwrites it

        // ---- write P tile (Ps[m][n], stride 65: conflict-free r/w) ----
        #pragma unroll
        for (int i = 0; i < 4; i++)
            #pragma unroll
            for (int j = 0; j < 4; j++)
                KPs[(4 * tm + i) * 65 + 4 * tn + j] = s[i][j];

        __syncthreads();

        // ---- PV GEMM: O += P V  (pairs packed along D) ----
        #pragma unroll 4
        for (int k = 0; k < 64; k++) {
            float p0 = KPs[(4 * tm + 0) * 65 + k];
            float p1 = KPs[(4 * tm + 1) * 65 + k];
            float p2 = KPs[(4 * tm + 2) * 65 + k];
            float p3 = KPs[(4 * tm + 3) * 65 + k];
            u64 v0 = *(const u64*)&Vs[k * 64 + 4 * tn];
            u64 v1 = *(const u64*)&Vs[k * 64 + 4 * tn + 2];
            u64 d0 = pk2(p0, p0), d1 = pk2(p1, p1);
            u64 d2 = pk2(p2, p2), d3 = pk2(p3, p3);
            o[0][0] = f2fma(d0, v0, o[0][0]); o[0][1] = f2fma(d0, v1, o[0][1]);
            o[1][0] = f2fma(d1, v0, o[1][0]); o[1][1] = f2fma(d1, v1, o[1][1]);
            o[2][0] = f2fma(d2, v0, o[2][0]); o[2][1] = f2fma(d2, v1, o[2][1]);
            o[3][0] = f2fma(d3, v0, o[3][0]); o[3][1] = f2fma(d3, v1, o[3][1]);
        }
        __syncthreads();   // done with Ps/Vs before next tile's loads
    }

    // ---- epilogue: normalize and store ctx[b, q, h*DK + d] ----
    #pragma unroll
    for (int i = 0; i < 4; i++) {
        float inv = 1.0f / lrow[i];
        float2 c0 = upk(o[i][0]);
        float2 c1 = upk(o[i][1]);
        size_t base = (size_t)(b * S_ + q0 + 4 * tm + i) * INNER_ + h * DK_ + 4 * tn;
        float4 out4 = make_float4(c0.x * inv, c0.y * inv, c1.x * inv, c1.y * inv);
        *(float4*)&ctx[base] = out4;
    }
}

// ---------------------------------------------------------------------------
// Host launcher
// ---------------------------------------------------------------------------
extern "C" void kernel_launch(void* const* d_in, const int* in_sizes, int n_in,
                              void* d_out, int out_size)
{
    const float* x     = (const float*)d_in[0];   // [B,S,DM]
    const int*   pos   = (const int*)d_in[1];     // [B,S] int32
    const float* mask  = (const float*)d_in[2];   // [B,S]
    const float* wq    = (const float*)d_in[3];   // [INNER,DM]
    const float* wk    = (const float*)d_in[4];
    const float* wv    = (const float*)d_in[5];
    const float* wo    = (const float*)d_in[6];   // [DM,INNER]
    const float* rbias = (const float*)d_in[7];   // [32,16]
    float*       out   = (float*)d_out;           // [B,S,DM]

    float *qp, *kp, *vp, *cp;
    cudaGetSymbolAddress((void**)&qp, g_q);
    cudaGetSymbolAddress((void**)&kp, g_k);
    cudaGetSymbolAddress((void**)&vp, g_v);
    cudaGetSymbolAddress((void**)&cp, g_ctx);

    cudaFuncSetAttribute(attn_kernel,
                         cudaFuncAttributeMaxDynamicSharedMemorySize,
                         ATT_SMEM_BYTES);

    dim3 gblk(256);

    // Stage 1: Q/K/V projections in one launch (z selects target)
    dim3 qkvgrid(INNER_ / 64, TOK_ / 128, 3);
    gemm_qkv<<<qkvgrid, gblk>>>(x, wq, wk, wv, qp, kp, vp);

    // Stage 2: fused flash attention with T5 relative bias
    dim3 agrid(S_ / 64, H_, B_);
    attn_kernel<<<agrid, 256, ATT_SMEM_BYTES>>>(qp, kp, vp, pos, mask, rbias, cp);

    // Stage 3: output projection
    dim3 ogrid(DM_ / 64, TOK_ / 128);
    gemm_nt<<<ogrid, gblk>>>(cp, wo, out, TOK_, DM_, DM_);
}

// round 10
// speedup vs baseline: 1.7766x; 1.7766x over previous
#include <cuda_runtime.h>

// ---------------------------------------------------------------------------
// T5 self-attention, fused:  out = Attn(X Wq^T, X Wk^T, X Wv^T) Wo^T
// R6-R9: raise register reuse (8x8 GEMM micro-tile, 8x4 attention micro-tile)
//     to move the bottleneck from the smem crossbar (L1=94.5%) to the FMA pipe.
// ---------------------------------------------------------------------------

#define B_     4
#define S_     2048
#define DM_    1024
#define H_     16
#define DK_    64
#define INNER_ 1024
#define TOK_   (B_ * S_)

typedef unsigned long long u64;

// ---- packed f32x2 helpers (Blackwell FFMA2 path) --------------------------
__device__ __forceinline__ u64 pk2(float lo, float hi) {
    u64 r; asm("mov.b64 %0, {%1, %2};" : "=l"(r) : "f"(lo), "f"(hi)); return r;
}
__device__ __forceinline__ float2 upk(u64 v) {
    float2 r; asm("mov.b64 {%0, %1}, %2;" : "=f"(r.x), "=f"(r.y) : "l"(v)); return r;
}
__device__ __forceinline__ u64 f2fma(u64 a, u64 b, u64 c) {
    u64 d; asm("fma.rn.f32x2 %0, %1, %2, %3;" : "=l"(d) : "l"(a), "l"(b), "l"(c)); return d;
}
__device__ __forceinline__ u64 f2mul(u64 a, u64 b) {
    u64 d; asm("mul.rn.f32x2 %0, %1, %2;" : "=l"(d) : "l"(a), "l"(b)); return d;
}

// ---- scratch (device globals: no allocations allowed) ---------------------
__device__ float g_q[TOK_ * INNER_];
__device__ float g_k[TOK_ * INNER_];
__device__ float g_v[TOK_ * INNER_];
__device__ float g_ctx[TOK_ * INNER_];

// ---------------------------------------------------------------------------
// GEMM core:  C[M,N] = A[M,K] * W[N,K]^T   (both operands K-contiguous)
// Block tile 128x128, BK=16, 256 threads, 8x8 per-thread micro-tile,
// f32x2 accumulators (pairs packed along M). FMA-bound under dedup model.
// Requires M%128==0, N%128==0, K%16==0.
// ---------------------------------------------------------------------------
__device__ __forceinline__ void gemm_nt_body(
    const float* __restrict__ A, const float* __restrict__ W,
    float* __restrict__ C, int M, int N, int K)
{
    __shared__ float As[16 * 128];   // [k][m]  (transposed)
    __shared__ float Ws[16 * 132];   // [k][n]  stride 132 (pad, 16B-aligned rows)

    const int tid = threadIdx.x;
    const int tn  = tid & 15;        // 0..15 -> 8 cols each
    const int tm  = tid >> 4;        // 0..15 -> 8 rows each
    const int bm  = blockIdx.y * 128;
    const int bn  = blockIdx.x * 128;
    const int KT  = K >> 4;

    // loader coordinates: each thread loads 2 float4 of A and 2 float4 of W
    const int lrow = tid >> 1;             // 0..127
    const int lk8  = (tid & 1) << 3;       // {0, 8}

    const float* Ap = A + (size_t)(bm + lrow) * K + lk8;
    const float* Wp = W + (size_t)(bn + lrow) * K + lk8;

    u64 acc[4][8];
    #pragma unroll
    for (int p = 0; p < 4; p++)
        #pragma unroll
        for (int j = 0; j < 8; j++) acc[p][j] = 0ull;

    float4 pa0 = *(const float4*)(Ap);
    float4 pa1 = *(const float4*)(Ap + 4);
    float4 pw0 = *(const float4*)(Wp);
    float4 pw1 = *(const float4*)(Wp + 4);

    for (int kt = 0; kt < KT; ++kt) {
        // stage regs -> smem (transpose into [k][*])
        {
            float a0[4], a1[4], w0[4], w1[4];
            *(float4*)a0 = pa0; *(float4*)a1 = pa1;
            *(float4*)w0 = pw0; *(float4*)w1 = pw1;
            #pragma unroll
            for (int c = 0; c < 4; c++) {
                As[(lk8 + c) * 128 + lrow]     = a0[c];
                As[(lk8 + 4 + c) * 128 + lrow] = a1[c];
                Ws[(lk8 + c) * 132 + lrow]     = w0[c];
                Ws[(lk8 + 4 + c) * 132 + lrow] = w1[c];
            }
        }
        __syncthreads();

        // prefetch next tile while computing this one
        if (kt + 1 < KT) {
            Ap += 16; Wp += 16;
            pa0 = *(const float4*)(Ap);
            pa1 = *(const float4*)(Ap + 4);
            pw0 = *(const float4*)(Wp);
            pw1 = *(const float4*)(Wp + 4);
        }

        #pragma unroll
        for (int k = 0; k < 16; k++) {
            float4 af0 = *(const float4*)&As[k * 128 + 8 * tm];
            float4 af1 = *(const float4*)&As[k * 128 + 8 * tm + 4];
            u64 a0 = ((const u64*)&af0)[0];
            u64 a1 = ((const u64*)&af0)[1];
            u64 a2 = ((const u64*)&af1)[0];
            u64 a3 = ((const u64*)&af1)[1];
            float4 w0 = *(const float4*)&Ws[k * 132 + 8 * tn];
            float4 w1 = *(const float4*)&Ws[k * 132 + 8 * tn + 4];
            u64 b0 = pk2(w0.x, w0.x), b1 = pk2(w0.y, w0.y);
            u64 b2 = pk2(w0.z, w0.z), b3 = pk2(w0.w, w0.w);
            u64 b4 = pk2(w1.x, w1.x), b5 = pk2(w1.y, w1.y);
            u64 b6 = pk2(w1.z, w1.z), b7 = pk2(w1.w, w1.w);
            #pragma unroll
            for (int p = 0; p < 4; p++) {
                u64 ap = (p == 0) ? a0 : (p == 1) ? a1 : (p == 2) ? a2 : a3;
                acc[p][0] = f2fma(ap, b0, acc[p][0]);
                acc[p][1] = f2fma(ap, b1, acc[p][1]);
                acc[p][2] = f2fma(ap, b2, acc[p][2]);
                acc[p][3] = f2fma(ap, b3, acc[p][3]);
                acc[p][4] = f2fma(ap, b4, acc[p][4]);
                acc[p][5] = f2fma(ap, b5, acc[p][5]);
                acc[p][6] = f2fma(ap, b6, acc[p][6]);
                acc[p][7] = f2fma(ap, b7, acc[p][7]);
            }
        }
        __syncthreads();
    }

    // epilogue: pair p covers rows (8*tm + 2p, +1); cols 8*tn .. +7
    #pragma unroll
    for (int p = 0; p < 4; p++) {
        float2 c0 = upk(acc[p][0]), c1 = upk(acc[p][1]);
        float2 c2 = upk(acc[p][2]), c3 = upk(acc[p][3]);
        float2 c4 = upk(acc[p][4]), c5 = upk(acc[p][5]);
        float2 c6 = upk(acc[p][6]), c7 = upk(acc[p][7]);
        int r0 = bm + 8 * tm + 2 * p;
        size_t base0 = (size_t)r0 * N + bn + 8 * tn;
        size_t base1 = base0 + N;
        *(float4*)&C[base0]     = make_float4(c0.x, c1.x, c2.x, c3.x);
        *(float4*)&C[base0 + 4] = make_float4(c4.x, c5.x, c6.x, c7.x);
        *(float4*)&C[base1]     = make_float4(c0.y, c1.y, c2.y, c3.y);
        *(float4*)&C[base1 + 4] = make_float4(c4.y, c5.y, c6.y, c7.y);
    }
}

// Plain GEMM (out projection)
__global__ void __launch_bounds__(256, 2) gemm_nt(
    const float* __restrict__ A, const float* __restrict__ W,
    float* __restrict__ C, int M, int N, int K)
{
    gemm_nt_body(A, W, C, M, N, K);
}

// Fused QKV: blockIdx.z selects weight + destination (one launch, 3x blocks)
__global__ void __launch_bounds__(256, 2) gemm_qkv(
    const float* __restrict__ A,
    const float* __restrict__ Wq, const float* __restrict__ Wk,
    const float* __restrict__ Wv,
    float* __restrict__ Q, float* __restrict__ Kd, float* __restrict__ V)
{
    const float* W; float* C;
    if (blockIdx.z == 0)      { W = Wq; C = Q;  }
    else if (blockIdx.z == 1) { W = Wk; C = Kd; }
    else                      { W = Wv; C = V;  }
    gemm_nt_body(A, W, C, TOK_, INNER_, DM_);
}

// ---------------------------------------------------------------------------
// T5 relative-position bucket (bidirectional, NUM_BUCKETS=32, MAX_DIST=128).
// log replaced by exact integer thresholds (verified vs fp32 reference).
// ---------------------------------------------------------------------------
__device__ __forceinline__ int t5_bucket(int d) {  // d = pos_key - pos_query
    int sgn = (d > 0) ? 16 : 0;
    int a = d < 0 ? -d : d;
    int r;
    if (a < 8) r = a;
    else r = 8 + (a >= 12) + (a >= 16) + (a >= 23) + (a >= 32)
               + (a >= 46) + (a >= 64) + (a >= 91);
    return sgn + r;
}

// ---------------------------------------------------------------------------
// Flash attention, one block per (q-tile of 128, head, batch).
// 256 threads as 16(tn) x 16(tm); 8(M) x 4(N) score micro-tile per thread.
// Smem: Qs [d][m] s128 | union{ Ks [d][n] s66 , Ps [m][k] s66 } | Vs [k][d] s64
// ---------------------------------------------------------------------------
#define ATT_SMEM_FLOATS (64*128 + 128*66 + 64*64 + 64 + 64 + 32)
#define ATT_SMEM_BYTES  (ATT_SMEM_FLOATS * 4)

__global__ void __launch_bounds__(256, 2) attn_kernel(
    const float* __restrict__ Qg, const float* __restrict__ Kg,
    const float* __restrict__ Vg,
    const int* __restrict__ positions, const float* __restrict__ mask,
    const float* __restrict__ rel_bias, float* __restrict__ ctx)
{
    extern __shared__ float smf[];
    float* Qs    = smf;                    // 64*128, [d][m] stride 128
    float* KPs   = Qs + 64 * 128;          // union: Ks 64x66 / Ps 128x66
    float* Vs    = KPs + 128 * 66;         // 64*64, [k][d]
    int*   posk  = (int*)(Vs + 64 * 64);   // 64
    float* maskb = (float*)(posk + 64);    // 64
    float* rb    = maskb + 64;             // 32

    const int tid = threadIdx.x;
    const int tn  = tid & 15;              // 4 n-cols: 4*tn..+3
    const int tm  = tid >> 4;              // 8 m-rows: 8*tm..+7
    const int qt  = blockIdx.x, h = blockIdx.y, b = blockIdx.z;
    const int q0  = qt * 128;

    if (tid < 32) rb[tid] = rel_bias[tid * H_ + h];

    // load Q tile (128 rows x 64 d, transposed to [d][m] stride 128)
    {
        const float* Qb = Qg + (size_t)(b * S_ + q0) * INNER_ + h * DK_;
        for (int idx = tid; idx < 128 * 16; idx += 256) {
            int row = idx >> 4, d4 = (idx & 15) << 2;
            float4 v = *(const float4*)(Qb + (size_t)row * INNER_ + d4);
            float a[4]; *(float4*)a = v;
            #pragma unroll
            for (int c = 0; c < 4; c++) Qs[(d4 + c) * 128 + row] = a[c];
        }
    }

    int posq[8];
    #pragma unroll
    for (int i = 0; i < 8; i++) posq[i] = positions[b * S_ + q0 + 8 * tm + i];

    u64 o[8][2];
    float mrow[8], lrow[8];
    const float NEG_INF = __int_as_float(0xff800000u);
    #pragma unroll
    for (int i = 0; i < 8; i++) {
        o[i][0] = 0ull; o[i][1] = 0ull; mrow[i] = NEG_INF; lrow[i] = 0.f;
    }

    __syncthreads();

    for (int kt = 0; kt < S_ / 64; ++kt) {
        const int k0 = kt * 64;
        // ---- load K (transposed, s66) and V (natural, s64) tiles ----
        {
            const float* Kb = Kg + (size_t)(b * S_ + k0) * INNER_ + h * DK_;
            const float* Vb = Vg + (size_t)(b * S_ + k0) * INNER_ + h * DK_;
            for (int idx = tid; idx < 64 * 16; idx += 256) {
                int row = idx >> 4, d4 = (idx & 15) << 2;
                float4 kv = *(const float4*)(Kb + (size_t)row * INNER_ + d4);
                float a[4]; *(float4*)a = kv;
                #pragma unroll
                for (int c = 0; c < 4; c++) KPs[(d4 + c) * 66 + row] = a[c];
                float4 vv = *(const float4*)(Vb + (size_t)row * INNER_ + d4);
                *(float4*)&Vs[row * 64 + d4] = vv;
            }
            if (tid < 64) {
                posk[tid]  = positions[b * S_ + k0 + tid];
                maskb[tid] = -1000.0f * (1.0f - mask[b * S_ + k0 + tid]);
            }
        }
        __syncthreads();

        // ---- score GEMM: S = Q K^T (pairs packed along M) ----
        u64 sa[4][4];
        #pragma unroll
        for (int p = 0; p < 4; p++)
            #pragma unroll
            for (int j = 0; j < 4; j++) sa[p][j] = 0ull;

        #pragma unroll 4
        for (int k = 0; k < 64; k++) {
            float4 qf0 = *(const float4*)&Qs[k * 128 + 8 * tm];
            float4 qf1 = *(const float4*)&Qs[k * 128 + 8 * tm + 4];
            u64 a0 = ((const u64*)&qf0)[0];
            u64 a1 = ((const u64*)&qf0)[1];
            u64 a2 = ((const u64*)&qf1)[0];
            u64 a3 = ((const u64*)&qf1)[1];
            u64 kw01 = *(const u64*)&KPs[k * 66 + 4 * tn];
            u64 kw23 = *(const u64*)&KPs[k * 66 + 4 * tn + 2];
            float2 w0 = upk(kw01), w1 = upk(kw23);
            u64 b0 = pk2(w0.x, w0.x), b1 = pk2(w0.y, w0.y);
            u64 b2 = pk2(w1.x, w1.x), b3 = pk2(w1.y, w1.y);
            sa[0][0] = f2fma(a0, b0, sa[0][0]); sa[0][1] = f2fma(a0, b1, sa[0][1]);
            sa[0][2] = f2fma(a0, b2, sa[0][2]); sa[0][3] = f2fma(a0, b3, sa[0][3]);
            sa[1][0] = f2fma(a1, b0, sa[1][0]); sa[1][1] = f2fma(a1, b1, sa[1][1]);
            sa[1][2] = f2fma(a1, b2, sa[1][2]); sa[1][3] = f2fma(a1, b3, sa[1][3]);
            sa[2][0] = f2fma(a2, b0, sa[2][0]); sa[2][1] = f2fma(a2, b1, sa[2][1]);
            sa[2][2] = f2fma(a2, b2, sa[2][2]); sa[2][3] = f2fma(a2, b3, sa[2][3]);
            sa[3][0] = f2fma(a3, b0, sa[3][0]); sa[3][1] = f2fma(a3, b1, sa[3][1]);
            sa[3][2] = f2fma(a3, b2, sa[3][2]); sa[3][3] = f2fma(a3, b3, sa[3][3]);
        }

        float s[8][4];
        #pragma unroll
        for (int p = 0; p < 4; p++)
            #pragma unroll
            for (int j = 0; j < 4; j++) {
                float2 t = upk(sa[p][j]);
                s[2 * p][j] = t.x; s[2 * p + 1][j] = t.y;
            }

        // ---- bias: relative-position bucket + mask ----
        #pragma unroll
        for (int j = 0; j < 4; j++) {
            int   nj = 4 * tn + j;
            int   pk = posk[nj];
            float mb = maskb[nj];
            #pragma unroll
            for (int i = 0; i < 8; i++) {
                int bkt = t5_bucket(pk - posq[i]);
                s[i][j] += rb[bkt] + mb;
            }
        }

        // ---- online softmax update (row groups = 16-lane segments) ----
        #pragma unroll
        for (int i = 0; i < 8; i++) {
            float mx = fmaxf(fmaxf(s[i][0], s[i][1]), fmaxf(s[i][2], s[i][3]));
            #pragma unroll
            for (int off = 8; off >= 1; off >>= 1)
                mx = fmaxf(mx, __shfl_xor_sync(0xffffffffu, mx, off, 16));
            float mnew  = fmaxf(mrow[i], mx);
            float alpha = __expf(mrow[i] - mnew);
            mrow[i] = mnew;
            float ps = 0.f;
            #pragma unroll
            for (int j = 0; j < 4; j++) {
                float p = __expf(s[i][j] - mnew);
                s[i][j] = p; ps += p;
            }
            #pragma unroll
            for (int off = 8; off >= 1; off >>= 1)
                ps += __shfl_xor_sync(0xffffffffu, ps, off, 16);
            lrow[i] = lrow[i] * alpha + ps;
            u64 al = pk2(alpha, alpha);
            o[i][0] = f2mul(o[i][0], al);
            o[i][1] = f2mul(o[i][1], al);
        }

        __syncthreads();   // everyone done reading Ks before P overwrites it

        // ---- write P tile (Ps[m][k] stride 66: even stride -> LDS.64 reads) ----
        #pragma unroll
        for (int i = 0; i < 8; i++)
            #pragma unroll
            for (int j = 0; j < 4; j++)
                KPs[(8 * tm + i) * 66 + 4 * tn + j] = s[i][j];

        __syncthreads();

        // ---- PV GEMM: O += P V  (k-pairs; pairs packed along D) ----
        #pragma unroll 2
        for (int k = 0; k < 64; k += 2) {
            float4 vf0 = *(const float4*)&Vs[k * 64 + 4 * tn];
            float4 vf1 = *(const float4*)&Vs[(k + 1) * 64 + 4 * tn];
            u64 v0a = ((const u64*)&vf0)[0];
            u64 v0b = ((const u64*)&vf0)[1];
            u64 v1a = ((const u64*)&vf1)[0];
            u64 v1b = ((const u64*)&vf1)[1];
            #pragma unroll
            for (int i = 0; i < 8; i++) {
                float2 p2 = *(const float2*)&KPs[(8 * tm + i) * 66 + k];
                u64 pa = pk2(p2.x, p2.x);
                u64 pb = pk2(p2.y, p2.y);
                o[i][0] = f2fma(pa, v0a, o[i][0]);
                o[i][1] = f2fma(pa, v0b, o[i][1]);
                o[i][0] = f2fma(pb, v1a, o[i][0]);
                o[i][1] = f2fma(pb, v1b, o[i][1]);
            }
        }
        __syncthreads();   // done with Ps/Vs before next tile's loads
    }

    // ---- epilogue: normalize and store ctx[b, q, h*DK + d] ----
    #pragma unroll
    for (int i = 0; i < 8; i++) {
        float inv = 1.0f / lrow[i];
        float2 c0 = upk(o[i][0]);
        float2 c1 = upk(o[i][1]);
        size_t base = (size_t)(b * S_ + q0 + 8 * tm + i) * INNER_ + h * DK_ + 4 * tn;
        float4 out4 = make_float4(c0.x * inv, c0.y * inv, c1.x * inv, c1.y * inv);
        *(float4*)&ctx[base] = out4;
    }
}

// ---------------------------------------------------------------------------
// Host launcher
// ---------------------------------------------------------------------------
extern "C" void kernel_launch(void* const* d_in, const int* in_sizes, int n_in,
                              void* d_out, int out_size)
{
    const float* x     = (const float*)d_in[0];   // [B,S,DM]
    const int*   pos   = (const int*)d_in[1];     // [B,S] int32
    const float* mask  = (const float*)d_in[2];   // [B,S]
    const float* wq    = (const float*)d_in[3];   // [INNER,DM]
    const float* wk    = (const float*)d_in[4];
    const float* wv    = (const float*)d_in[5];
    const float* wo    = (const float*)d_in[6];   // [DM,INNER]
    const float* rbias = (const float*)d_in[7];   // [32,16]
    float*       out   = (float*)d_out;           // [B,S,DM]

    float *qp, *kp, *vp, *cp;
    cudaGetSymbolAddress((void**)&qp, g_q);
    cudaGetSymbolAddress((void**)&kp, g_k);
    cudaGetSymbolAddress((void**)&vp, g_v);
    cudaGetSymbolAddress((void**)&cp, g_ctx);

    cudaFuncSetAttribute(attn_kernel,
                         cudaFuncAttributeMaxDynamicSharedMemorySize,
                         ATT_SMEM_BYTES);

    dim3 gblk(256);

    // Stage 1: Q/K/V projections in one launch (z selects target)
    dim3 qkvgrid(INNER_ / 128, TOK_ / 128, 3);
    gemm_qkv<<<qkvgrid, gblk>>>(x, wq, wk, wv, qp, kp, vp);

    // Stage 2: fused flash attention with T5 relative bias
    dim3 agrid(S_ / 128, H_, B_);
    attn_kernel<<<agrid, 256, ATT_SMEM_BYTES>>>(qp, kp, vp, pos, mask, rbias, cp);

    // Stage 3: output projection
    dim3 ogrid(DM_ / 128, TOK_ / 128);
    gemm_nt<<<ogrid, gblk>>>(cp, wo, out, TOK_, DM_, DM_);
}